// round 4
// baseline (speedup 1.0000x reference)
#include <cuda_runtime.h>
#include <math.h>

#define K 64
#define D 64
#define STRIDE 66            // padded k-stride for transposed tiles (even -> 8B aligned pairs)
#define GS 66                // row stride for gR[k][d]
#define ROWS_PER_CTA 8
#define NTHREADS 256
#define ALPHA 0.2f
#define NEG_INF -9e15f
#define EPS 1e-8f

struct SmemT {
    float W1t[D * D];        // W1t[j][d] = fc_w[d][j]
    float W2t[D * D];        // W2t[j][d] = fc_w[d][64+j]
    float bias[D];
    float dstT[D * STRIDE];  // dstT[j][k] = dst[k][j]
    float relT[D * STRIDE];
    float gR[K * GS];        // gR[k][d]  = g[k][d] = (W2 dst[k] + b)[d]
    float sS[D];
    float uS[D];
    float grS[K];            // g.rel
    float ggS[K];            // ||g||^2
    float rynS[K];           // max(||rel||, eps)
    float eS[K];             // logits -> exp(p)
    float pA[4 * 64];
    float pB[4 * 64];
    float red[8];
    int   mk[K];
};

typedef unsigned long long ull;

__device__ __forceinline__ ull pack2(float x, float y) {
    ull r;
    asm("mov.b64 %0, {%1, %2};" : "=l"(r) : "f"(x), "f"(y));
    return r;
}
__device__ __forceinline__ void ffma2(ull &d, ull a, ull b) {
    asm("fma.rn.f32x2 %0, %1, %2, %0;" : "+l"(d) : "l"(a), "l"(b));
}

__global__ void __launch_bounds__(NTHREADS, 2)
kgat_fused_kernel(const float* __restrict__ src,
                  const float* __restrict__ dst,
                  const float* __restrict__ rel,
                  const float* __restrict__ fcw,
                  const float* __restrict__ fcb,
                  const int*   __restrict__ mask,
                  float* __restrict__ out,
                  int N, int Nout)
{
    extern __shared__ __align__(16) char smem_raw[];
    SmemT* sm = reinterpret_cast<SmemT*>(smem_raw);

    const int t = threadIdx.x;
    const int w = t >> 5;
    const int l = t & 31;

    // ---- CTA init: transpose fc_w into W1t / W2t, load bias ----
    for (int idx = t; idx < D * 2 * D; idx += NTHREADS) {
        int dd = idx >> 7;         // row of fc_w (output dim)
        int f  = idx & 127;        // input-feature index
        float v = fcw[idx];
        if (f < 64) sm->W1t[f * D + dd] = v;
        else        sm->W2t[(f - 64) * D + dd] = v;
    }
    if (t < D) sm->bias[t] = fcb[t];
    __syncthreads();

    // GEMM tile mapping: thread -> (k0 = 4*kt, d0 = 4*dg)
    const int kt = (t >> 2) & 15;
    const int k0 = kt * 4;
    const int dg = (t & 3) | ((t >> 6) << 2);
    const int d0 = dg * 4;

    const int n0 = blockIdx.x * ROWS_PER_CTA;

    for (int r = 0; r < ROWS_PER_CTA; ++r) {
        const int n = n0 + r;
        if (n >= N) break;  // uniform per CTA

        // ================= Phase 1: loads (transposed) =================
        {
            const float* dg_ = dst + (size_t)n * (K * D);
            const float* rg  = rel + (size_t)n * (K * D);
            float vd[16], vr[16];
            #pragma unroll
            for (int rr = 0; rr < 8; ++rr) {
                int k = w * 8 + rr;
                vd[2*rr]   = dg_[k * D + l];
                vd[2*rr+1] = dg_[k * D + 32 + l];
                vr[2*rr]   = rg[k * D + l];
                vr[2*rr+1] = rg[k * D + 32 + l];
            }
            #pragma unroll
            for (int rr = 0; rr < 8; ++rr) {
                int k = w * 8 + rr;
                sm->dstT[l * STRIDE + k]        = vd[2*rr];
                sm->dstT[(32 + l) * STRIDE + k] = vd[2*rr+1];
                sm->relT[l * STRIDE + k]        = vr[2*rr];
                sm->relT[(32 + l) * STRIDE + k] = vr[2*rr+1];
            }
            if (t < D) sm->sS[t] = src[(size_t)n * D + t];
        }
        __syncthreads();

        // ===== Phase 2: g GEMM, 4k x 4d register tile, f32x2 over d =====
        {
            ull b01 = pack2(sm->bias[d0],     sm->bias[d0 + 1]);
            ull b23 = pack2(sm->bias[d0 + 2], sm->bias[d0 + 3]);
            ull acc[4][2];
            #pragma unroll
            for (int kk = 0; kk < 4; ++kk) { acc[kk][0] = b01; acc[kk][1] = b23; }

            #pragma unroll 4
            for (int j = 0; j < D; ++j) {
                float2 dA = *reinterpret_cast<const float2*>(&sm->dstT[j * STRIDE + k0]);
                float2 dB = *reinterpret_cast<const float2*>(&sm->dstT[j * STRIDE + k0 + 2]);
                ulonglong2 wv = *reinterpret_cast<const ulonglong2*>(&sm->W2t[j * D + d0]);
                ull p0 = pack2(dA.x, dA.x);
                ull p1 = pack2(dA.y, dA.y);
                ull p2 = pack2(dB.x, dB.x);
                ull p3 = pack2(dB.y, dB.y);
                ffma2(acc[0][0], p0, wv.x); ffma2(acc[0][1], p0, wv.y);
                ffma2(acc[1][0], p1, wv.x); ffma2(acc[1][1], p1, wv.y);
                ffma2(acc[2][0], p2, wv.x); ffma2(acc[2][1], p2, wv.y);
                ffma2(acc[3][0], p3, wv.x); ffma2(acc[3][1], p3, wv.y);
            }
            #pragma unroll
            for (int kk = 0; kk < 4; ++kk) {
                *reinterpret_cast<ull*>(&sm->gR[(k0 + kk) * GS + d0])     = acc[kk][0];
                *reinterpret_cast<ull*>(&sm->gR[(k0 + kk) * GS + d0 + 2]) = acc[kk][1];
            }
        }
        __syncthreads();

        // ================= Phase 3: per-k row stats ====================
        if (t < 64) {
            int k = t;
            float a = 0.f, b = 0.f;
            #pragma unroll 8
            for (int dd = 0; dd < D; dd += 2) {
                float2 g2 = *reinterpret_cast<const float2*>(&sm->gR[k * GS + dd]);
                float r0 = sm->relT[dd * STRIDE + k];
                float r1 = sm->relT[(dd + 1) * STRIDE + k];
                a += g2.x * r0 + g2.y * r1;
                b += g2.x * g2.x + g2.y * g2.y;
            }
            sm->grS[k] = a;
            sm->ggS[k] = b;
        } else if (t < 128) {
            int k = t - 64;
            float rn = 0.f;
            #pragma unroll 8
            for (int dd = 0; dd < D; ++dd) {
                float rv = sm->relT[dd * STRIDE + k];
                rn += rv * rv;
            }
            sm->rynS[k] = fmaxf(sqrtf(rn), EPS);
        } else if (t < 192) {
            sm->mk[t - 128] = mask[(size_t)n * K + (t - 128)];
        }
        __syncthreads();

        // ================= Two GAT layers =============================
        #pragma unroll 1
        for (int layer = 0; layer < 2; ++layer) {
            // ---- u = W1 s (partials across 4 groups) ----
            {
                int dd = t & 63, p = t >> 6;
                float a = 0.f;
                #pragma unroll
                for (int j = p * 16; j < p * 16 + 16; ++j)
                    a += sm->sS[j] * sm->W1t[j * D + dd];
                sm->pA[p * 64 + dd] = a;
            }
            __syncthreads();
            if (t < 64)
                sm->uS[t] = sm->pA[t] + sm->pA[64 + t] + sm->pA[128 + t] + sm->pA[192 + t];
            __syncthreads();
            // ---- uu = ||u||^2 ----
            if (t < 64) {
                float v = sm->uS[t] * sm->uS[t];
                #pragma unroll
                for (int o = 16; o > 0; o >>= 1)
                    v += __shfl_xor_sync(0xffffffffu, v, o);
                if ((t & 31) == 0) sm->red[t >> 5] = v;
            }
            __syncthreads();
            const float uu = sm->red[0] + sm->red[1];

            // ---- per-k: u.rel and u.g partials ----
            {
                int k = t & 63, p = t >> 6, x0 = p * 16;
                float a = 0.f, c = 0.f;
                #pragma unroll
                for (int x = 0; x < 16; x += 2) {
                    float2 u2 = *reinterpret_cast<const float2*>(&sm->uS[x0 + x]);
                    float r0 = sm->relT[(x0 + x) * STRIDE + k];
                    float r1 = sm->relT[(x0 + x + 1) * STRIDE + k];
                    float2 g2 = *reinterpret_cast<const float2*>(&sm->gR[k * GS + x0 + x]);
                    a += u2.x * r0 + u2.y * r1;
                    c += u2.x * g2.x + u2.y * g2.y;
                }
                sm->pA[p * 64 + k] = a;
                sm->pB[p * 64 + k] = c;
            }
            __syncthreads();
            if (t < 64) {
                int k = t;
                float ur = sm->pA[k] + sm->pA[64 + k] + sm->pA[128 + k] + sm->pA[192 + k];
                float ug = sm->pB[k] + sm->pB[64 + k] + sm->pB[128 + k] + sm->pB[192 + k];
                float hr = ur + sm->grS[k];
                float hh = uu + 2.f * ug + sm->ggS[k];
                float xn = sqrtf(fmaxf(hh, 0.f));
                float cs = hr / (fmaxf(xn, EPS) * sm->rynS[k]);
                float el = cs > 0.f ? cs : ALPHA * cs;
                sm->eS[k] = (sm->mk[k] > 0) ? el : NEG_INF;
            }
            __syncthreads();
            // ---- softmax over K (2-warp reduce) ----
            if (t < 64) {
                float m = sm->eS[t];
                #pragma unroll
                for (int o = 16; o > 0; o >>= 1)
                    m = fmaxf(m, __shfl_xor_sync(0xffffffffu, m, o));
                if ((t & 31) == 0) sm->red[t >> 5] = m;
            }
            __syncthreads();
            if (t < 64) {
                float M = fmaxf(sm->red[0], sm->red[1]);
                float p_ = __expf(sm->eS[t] - M);
                sm->eS[t] = p_;
                float s = p_;
                #pragma unroll
                for (int o = 16; o > 0; o >>= 1)
                    s += __shfl_xor_sync(0xffffffffu, s, o);
                if ((t & 31) == 0) sm->red[2 + (t >> 5)] = s;
            }
            __syncthreads();
            const float denom = sm->red[2] + sm->red[3];

            // ---- agg = sum_k att[k] * dst[k] (normalize at the end) ----
            {
                int dd = t & 63, p = t >> 6;
                float a = 0.f;
                #pragma unroll
                for (int k2 = p * 16; k2 < p * 16 + 16; ++k2)
                    a += sm->eS[k2] * sm->dstT[dd * STRIDE + k2];
                sm->pA[p * 64 + dd] = a;
            }
            __syncthreads();
            if (t < 64) {
                float agg = (sm->pA[t] + sm->pA[64 + t] + sm->pA[128 + t] + sm->pA[192 + t]) / denom;
                float o = agg + sm->sS[t];
                if (layer == 0) {
                    sm->sS[t] = o;           // feed layer 2
                } else if (n < Nout) {
                    out[(size_t)n * D + t] = o;
                }
            }
            __syncthreads();
        }
    }
}

extern "C" void kernel_launch(void* const* d_in, const int* in_sizes, int n_in,
                              void* d_out, int out_size)
{
    const float* src = (const float*)d_in[0];
    const float* dst = (const float*)d_in[1];
    const float* rel = (const float*)d_in[2];
    const float* fcw = (const float*)d_in[3];
    const float* fcb = (const float*)d_in[4];
    const int*   msk = (const int*)d_in[5];
    float* out = (float*)d_out;

    const int N = in_sizes[0] / D;
    const int Nout = out_size / D;

    const int smem_bytes = (int)sizeof(SmemT);
    cudaFuncSetAttribute(kgat_fused_kernel,
                         cudaFuncAttributeMaxDynamicSharedMemorySize, smem_bytes);

    const int blocks = (N + ROWS_PER_CTA - 1) / ROWS_PER_CTA;
    kgat_fused_kernel<<<blocks, NTHREADS, smem_bytes>>>(src, dst, rel, fcw, fcb,
                                                        msk, out, N, Nout);
}

// round 5
// speedup vs baseline: 1.9608x; 1.9608x over previous
#include <cuda_runtime.h>
#include <cuda_bf16.h>
#include <math.h>

#define K 64
#define D 64
#define AS 72                // bf16 row stride (bytes*2=144: 8 consecutive rows -> distinct bank groups)
#define GS 66                // fp32 row stride for gR / relR
#define ROWS_PER_CTA 8
#define NT 256
#define ALPHA 0.2f
#define NEG_INF -9e15f
#define EPS 1e-8f

struct __align__(16) SmemT {
    float W1t[D * D];              // W1t[j][d] = fc_w[d][j]
    float bias[D];
    __nv_bfloat16 W2hiT[D * AS];   // W2T[d][j] = fc_w[d][64+j], hi part
    __nv_bfloat16 W2loT[D * AS];
    __nv_bfloat16 Ahi[K * AS];     // Ahi[k][j] = bf16(dst[k][j])
    __nv_bfloat16 Alo[K * AS];
    float relR[K * GS];            // relR[k][d]
    float gR[K * GS];              // gR[k][d]
    float sS[D];
    float uS[D];
    float grS[K], ggS[K], rynS[K], eS[K];
    float pA[256], pB[256], pC[256];
    float red[8];
    int   mk[K];
};

__device__ __forceinline__ unsigned smem_u32(const void* p) {
    unsigned a;
    asm("{ .reg .u64 t; cvta.to.shared.u64 t, %1; cvt.u32.u64 %0, t; }" : "=r"(a) : "l"(p));
    return a;
}
__device__ __forceinline__ void ldmx4(unsigned* r, unsigned addr) {
    asm volatile("ldmatrix.sync.aligned.m8n8.x4.shared.b16 {%0,%1,%2,%3}, [%4];"
                 : "=r"(r[0]), "=r"(r[1]), "=r"(r[2]), "=r"(r[3]) : "r"(addr));
}
__device__ __forceinline__ void ldmx2(unsigned* r, unsigned addr) {
    asm volatile("ldmatrix.sync.aligned.m8n8.x2.shared.b16 {%0,%1}, [%2];"
                 : "=r"(r[0]), "=r"(r[1]) : "r"(addr));
}
__device__ __forceinline__ void mma16816(float* c, const unsigned* a, const unsigned* b) {
    asm volatile("mma.sync.aligned.m16n8k16.row.col.f32.bf16.bf16.f32 "
                 "{%0,%1,%2,%3}, {%4,%5,%6,%7}, {%8,%9}, {%0,%1,%2,%3};"
                 : "+f"(c[0]), "+f"(c[1]), "+f"(c[2]), "+f"(c[3])
                 : "r"(a[0]), "r"(a[1]), "r"(a[2]), "r"(a[3]), "r"(b[0]), "r"(b[1]));
}
__device__ __forceinline__ unsigned pkbf(float a, float b) {
    __nv_bfloat162 h = __floats2bfloat162_rn(a, b);
    return *reinterpret_cast<unsigned*>(&h);
}

__global__ void __launch_bounds__(NT, 2)
kgat_mma_kernel(const float* __restrict__ src,
                const float* __restrict__ dst,
                const float* __restrict__ rel,
                const float* __restrict__ fcw,
                const float* __restrict__ fcb,
                const int*   __restrict__ mask,
                float* __restrict__ out,
                int N, int Nout)
{
    extern __shared__ __align__(16) char smem_raw[];
    SmemT* sm = reinterpret_cast<SmemT*>(smem_raw);

    const int t = threadIdx.x;
    const int w = t >> 5;
    const int l = t & 31;

    // ---- CTA init: W1t fp32 transpose; W2 -> bf16 hi/lo (d-major); bias ----
    for (int idx = t; idx < D * D; idx += NT) {
        int dd = idx >> 6, j = idx & 63;
        sm->W1t[j * D + dd] = fcw[dd * 128 + j];
    }
    for (int c = t; c < 512; c += NT) {
        int dd = c >> 3, j0 = (c & 7) * 8;
        const float* wp = fcw + dd * 128 + 64 + j0;
        float4 v0 = *reinterpret_cast<const float4*>(wp);
        float4 v1 = *reinterpret_cast<const float4*>(wp + 4);
        float vv[8] = {v0.x, v0.y, v0.z, v0.w, v1.x, v1.y, v1.z, v1.w};
        float hv[8], lv[8];
        #pragma unroll
        for (int q = 0; q < 8; ++q) {
            hv[q] = __bfloat162float(__float2bfloat16_rn(vv[q]));
            lv[q] = vv[q] - hv[q];
        }
        *reinterpret_cast<uint4*>(&sm->W2hiT[dd * AS + j0]) =
            make_uint4(pkbf(hv[0],hv[1]), pkbf(hv[2],hv[3]), pkbf(hv[4],hv[5]), pkbf(hv[6],hv[7]));
        *reinterpret_cast<uint4*>(&sm->W2loT[dd * AS + j0]) =
            make_uint4(pkbf(lv[0],lv[1]), pkbf(lv[2],lv[3]), pkbf(lv[4],lv[5]), pkbf(lv[6],lv[7]));
    }
    if (t < D) sm->bias[t] = fcb[t];
    __syncthreads();

    const int n0b = blockIdx.x * ROWS_PER_CTA;

    for (int r = 0; r < ROWS_PER_CTA; ++r) {
        const int n = n0b + r;
        if (n >= N) break;  // uniform per CTA

        // ========== Stage: dst -> Ahi/Alo bf16; rel -> relR; src; mask ==========
        {
            const float* dp_ = dst + (size_t)n * (K * D);
            #pragma unroll
            for (int i = 0; i < 2; ++i) {
                int c = t + i * 256;                // 0..511
                int k = c >> 3, j0 = (c & 7) * 8;
                float4 v0 = *reinterpret_cast<const float4*>(dp_ + k * D + j0);
                float4 v1 = *reinterpret_cast<const float4*>(dp_ + k * D + j0 + 4);
                float vv[8] = {v0.x, v0.y, v0.z, v0.w, v1.x, v1.y, v1.z, v1.w};
                float hv[8], lv[8];
                #pragma unroll
                for (int q = 0; q < 8; ++q) {
                    hv[q] = __bfloat162float(__float2bfloat16_rn(vv[q]));
                    lv[q] = vv[q] - hv[q];
                }
                *reinterpret_cast<uint4*>(&sm->Ahi[k * AS + j0]) =
                    make_uint4(pkbf(hv[0],hv[1]), pkbf(hv[2],hv[3]), pkbf(hv[4],hv[5]), pkbf(hv[6],hv[7]));
                *reinterpret_cast<uint4*>(&sm->Alo[k * AS + j0]) =
                    make_uint4(pkbf(lv[0],lv[1]), pkbf(lv[2],lv[3]), pkbf(lv[4],lv[5]), pkbf(lv[6],lv[7]));
            }
            const float* rp = rel + (size_t)n * (K * D);
            #pragma unroll
            for (int i = 0; i < 4; ++i) {
                int f4 = t + i * 256;               // 0..1023
                int k = f4 >> 4, q = (f4 & 15) * 4;
                float4 v = *reinterpret_cast<const float4*>(rp + k * D + q);
                *reinterpret_cast<float2*>(&sm->relR[k * GS + q])     = make_float2(v.x, v.y);
                *reinterpret_cast<float2*>(&sm->relR[k * GS + q + 2]) = make_float2(v.z, v.w);
            }
            if (t < 64)       sm->sS[t] = src[(size_t)n * D + t];
            else if (t < 128) sm->mk[t - 64] = mask[(size_t)n * K + (t - 64)];
        }
        __syncthreads();

        // ========== g GEMM via mma.sync bf16-split: gR = dst*W2^T + bias ==========
        {
            const int m0 = (w & 1) * 32;            // warp quadrant: 2 m-tiles x 2 n-tiles
            const int nq0 = (w >> 1) * 16;
            const int tg = l & 3, gid = l >> 2;
            const int arow = ((l & 8) ? 8 : 0) + (l & 7);
            const int acol8 = (l & 16) ? 8 : 0;
            const int l4 = l & 15;
            const int brow = l4 & 7;
            const int bcol8 = (l4 & 8) ? 8 : 0;

            float c[2][2][4];
            #pragma unroll
            for (int ni = 0; ni < 2; ++ni) {
                float2 b2 = *reinterpret_cast<const float2*>(&sm->bias[nq0 + ni * 8 + tg * 2]);
                #pragma unroll
                for (int mi = 0; mi < 2; ++mi) {
                    c[mi][ni][0] = b2.x; c[mi][ni][1] = b2.y;
                    c[mi][ni][2] = b2.x; c[mi][ni][3] = b2.y;
                }
            }
            const unsigned ahi_b = smem_u32(sm->Ahi), alo_b = smem_u32(sm->Alo);
            const unsigned wh_b  = smem_u32(sm->W2hiT), wl_b = smem_u32(sm->W2loT);

            #pragma unroll
            for (int kc = 0; kc < 4; ++kc) {
                unsigned ah[2][4], al[2][4];
                #pragma unroll
                for (int mi = 0; mi < 2; ++mi) {
                    unsigned off = ((m0 + mi * 16 + arow) * AS + kc * 16 + acol8) * 2;
                    ldmx4(ah[mi], ahi_b + off);
                    ldmx4(al[mi], alo_b + off);
                }
                #pragma unroll
                for (int ni = 0; ni < 2; ++ni) {
                    unsigned boff = ((nq0 + ni * 8 + brow) * AS + kc * 16 + bcol8) * 2;
                    unsigned bh[2], bl[2];
                    ldmx2(bh, wh_b + boff);
                    ldmx2(bl, wl_b + boff);
                    #pragma unroll
                    for (int mi = 0; mi < 2; ++mi) {
                        mma16816(c[mi][ni], ah[mi], bh);
                        mma16816(c[mi][ni], ah[mi], bl);
                        mma16816(c[mi][ni], al[mi], bh);
                    }
                }
            }
            #pragma unroll
            for (int mi = 0; mi < 2; ++mi)
                #pragma unroll
                for (int ni = 0; ni < 2; ++ni) {
                    int row = m0 + mi * 16 + gid;
                    int col = nq0 + ni * 8 + tg * 2;
                    *reinterpret_cast<float2*>(&sm->gR[row * GS + col]) =
                        make_float2(c[mi][ni][0], c[mi][ni][1]);
                    *reinterpret_cast<float2*>(&sm->gR[(row + 8) * GS + col]) =
                        make_float2(c[mi][ni][2], c[mi][ni][3]);
                }
        }
        __syncthreads();

        // ========== per-k stats: g.rel, ||g||^2, ||rel|| ==========
        {
            int k = t & 63, p = t >> 6, d0 = p * 16;
            float gr = 0.f, gg = 0.f, rr = 0.f;
            #pragma unroll
            for (int d = 0; d < 16; d += 2) {
                float2 g2 = *reinterpret_cast<const float2*>(&sm->gR[k * GS + d0 + d]);
                float2 r2 = *reinterpret_cast<const float2*>(&sm->relR[k * GS + d0 + d]);
                gr += g2.x * r2.x + g2.y * r2.y;
                gg += g2.x * g2.x + g2.y * g2.y;
                rr += r2.x * r2.x + r2.y * r2.y;
            }
            sm->pA[p * 64 + k] = gr;
            sm->pB[p * 64 + k] = gg;
            sm->pC[p * 64 + k] = rr;
        }
        __syncthreads();
        if (t < 64) {
            sm->grS[t] = sm->pA[t] + sm->pA[64 + t] + sm->pA[128 + t] + sm->pA[192 + t];
            sm->ggS[t] = sm->pB[t] + sm->pB[64 + t] + sm->pB[128 + t] + sm->pB[192 + t];
            float rr = sm->pC[t] + sm->pC[64 + t] + sm->pC[128 + t] + sm->pC[192 + t];
            sm->rynS[t] = fmaxf(sqrtf(rr), EPS);
        }
        __syncthreads();

        // ========== two GAT layers ==========
        #pragma unroll 1
        for (int layer = 0; layer < 2; ++layer) {
            { // u = W1 s
                int dd = t & 63, p = t >> 6;
                float a = 0.f;
                #pragma unroll
                for (int j = p * 16; j < p * 16 + 16; ++j)
                    a += sm->sS[j] * sm->W1t[j * D + dd];
                sm->pA[p * 64 + dd] = a;
            }
            __syncthreads();
            if (t < 64) {
                float u = sm->pA[t] + sm->pA[64 + t] + sm->pA[128 + t] + sm->pA[192 + t];
                sm->uS[t] = u;
                float v = u * u;
                #pragma unroll
                for (int o = 16; o > 0; o >>= 1)
                    v += __shfl_xor_sync(0xffffffffu, v, o);
                if ((t & 31) == 0) sm->red[t >> 5] = v;
            }
            __syncthreads();
            const float uu = sm->red[0] + sm->red[1];

            { // u.rel, u.g per k
                int k = t & 63, p = t >> 6, d0 = p * 16;
                float ur = 0.f, ug = 0.f;
                #pragma unroll
                for (int d = 0; d < 16; d += 2) {
                    float2 u2 = *reinterpret_cast<const float2*>(&sm->uS[d0 + d]);
                    float2 r2 = *reinterpret_cast<const float2*>(&sm->relR[k * GS + d0 + d]);
                    float2 g2 = *reinterpret_cast<const float2*>(&sm->gR[k * GS + d0 + d]);
                    ur += u2.x * r2.x + u2.y * r2.y;
                    ug += u2.x * g2.x + u2.y * g2.y;
                }
                sm->pA[p * 64 + k] = ur;
                sm->pB[p * 64 + k] = ug;
            }
            __syncthreads();
            if (t < 64) {
                int k = t;
                float ur = sm->pA[k] + sm->pA[64 + k] + sm->pA[128 + k] + sm->pA[192 + k];
                float ug = sm->pB[k] + sm->pB[64 + k] + sm->pB[128 + k] + sm->pB[192 + k];
                float hr = ur + sm->grS[k];
                float hh = uu + 2.f * ug + sm->ggS[k];
                float xn = sqrtf(fmaxf(hh, 0.f));
                float cs = hr / (fmaxf(xn, EPS) * sm->rynS[k]);
                float el = cs > 0.f ? cs : ALPHA * cs;
                sm->eS[k] = (sm->mk[k] > 0) ? el : NEG_INF;
            }
            __syncthreads();
            if (t < 64) { // softmax max
                float m = sm->eS[t];
                #pragma unroll
                for (int o = 16; o > 0; o >>= 1)
                    m = fmaxf(m, __shfl_xor_sync(0xffffffffu, m, o));
                if ((t & 31) == 0) sm->red[t >> 5] = m;
            }
            __syncthreads();
            if (t < 64) { // exp + sum
                float M = fmaxf(sm->red[0], sm->red[1]);
                float p_ = __expf(sm->eS[t] - M);
                sm->eS[t] = p_;
                float s = p_;
                #pragma unroll
                for (int o = 16; o > 0; o >>= 1)
                    s += __shfl_xor_sync(0xffffffffu, s, o);
                if ((t & 31) == 0) sm->red[2 + (t >> 5)] = s;
            }
            __syncthreads();
            const float denom = sm->red[2] + sm->red[3];

            { // agg = sum_k e[k]*dst[k][dd], dst reconstructed = Ahi + Alo
                int dd = t & 63, p = t >> 6;
                float a = 0.f;
                #pragma unroll
                for (int k2 = p * 16; k2 < p * 16 + 16; ++k2) {
                    float v = __bfloat162float(sm->Ahi[k2 * AS + dd]) +
                              __bfloat162float(sm->Alo[k2 * AS + dd]);
                    a += sm->eS[k2] * v;
                }
                sm->pA[p * 64 + dd] = a;
            }
            __syncthreads();
            if (t < 64) {
                float agg = (sm->pA[t] + sm->pA[64 + t] + sm->pA[128 + t] + sm->pA[192 + t]) / denom;
                float o = agg + sm->sS[t];
                if (layer == 0)    sm->sS[t] = o;
                else if (n < Nout) out[(size_t)n * D + t] = o;
            }
            __syncthreads();
        }
    }
}

extern "C" void kernel_launch(void* const* d_in, const int* in_sizes, int n_in,
                              void* d_out, int out_size)
{
    const float* src = (const float*)d_in[0];
    const float* dst = (const float*)d_in[1];
    const float* rel = (const float*)d_in[2];
    const float* fcw = (const float*)d_in[3];
    const float* fcb = (const float*)d_in[4];
    const int*   msk = (const int*)d_in[5];
    float* out = (float*)d_out;

    const int N = in_sizes[0] / D;
    const int Nout = out_size / D;

    const int smem_bytes = (int)sizeof(SmemT);
    cudaFuncSetAttribute(kgat_mma_kernel,
                         cudaFuncAttributeMaxDynamicSharedMemorySize, smem_bytes);

    const int blocks = (N + ROWS_PER_CTA - 1) / ROWS_PER_CTA;
    kgat_mma_kernel<<<blocks, NT, smem_bytes>>>(src, dst, rel, fcw, fcb, msk, out, N, Nout);
}